// round 8
// baseline (speedup 1.0000x reference)
#include <cuda_runtime.h>
#include <cuda_bf16.h>
#include <math.h>

#define NMAX   100000
#define ETOTMX 1700000
#define SCAN_CHUNK 1024
#define SCAN_NB_MAX 128

// ---------------- scratch (static device globals; no allocation) ----------
__device__ int   g_is64;
__device__ int   g_src[ETOTMX];
__device__ int   g_dst[ETOTMX];
__device__ int   g_csr[ETOTMX];
__device__ int   g_dstc[ETOTMX];     // dst id per CSR slot (nearly sorted)
__device__ float g_w[ETOTMX];        // per-edge softmax numerator
__device__ int   g_deg[NMAX];
__device__ int   g_cnt[NMAX];
__device__ int   g_rowptr[NMAX + 1];
__device__ int   g_bsum[SCAN_NB_MAX];
__device__ int   g_boff[SCAN_NB_MAX];
__device__ __align__(16) float g_h[NMAX * 64];
__device__ __align__(16) float g_agg[NMAX * 64];
__device__ float g_as[NMAX];
__device__ float g_ad[NMAX];

// ---------------- dtype sniff: int64 vs int32 edge_index -------------------
__global__ void detect_kernel(const int* __restrict__ ei32) {
    if (threadIdx.x == 0) {
        int ok = 1;
        for (int i = 0; i < 256; i++)
            if (ei32[2 * i + 1] != 0) { ok = 0; break; }
        g_is64 = ok;
    }
}

// ---------------- graph build ---------------------------------------------
__global__ void zero_counts_kernel(int nN) {
    int i = blockIdx.x * blockDim.x + threadIdx.x;
    if (i < nN) { g_deg[i] = 0; g_cnt[i] = 0; }
}

__global__ void build_edges_kernel(const void* __restrict__ ei, int E, int Etot, int nN) {
    int i = blockIdx.x * blockDim.x + threadIdx.x;
    if (i >= Etot) return;
    int s, d;
    if (i < E) {
        if (g_is64) {
            const long long* p = (const long long*)ei;
            s = (int)p[i]; d = (int)p[E + i];
        } else {
            const int* p = (const int*)ei;
            s = p[i]; d = p[E + i];
        }
        s = min(max(s, 0), nN - 1);
        d = min(max(d, 0), nN - 1);
    } else {
        s = d = i - E;                 // self loops appended
    }
    g_src[i] = s;
    g_dst[i] = d;
    atomicAdd(&g_deg[d], 1);
}

// ---------------- multi-block exclusive scan: g_deg -> g_rowptr ------------
__global__ void scan_partial_kernel(int nN) {
    int b = blockIdx.x, tid = threadIdx.x;
    int base = b * SCAN_CHUNK + tid * 4;
    int s = 0;
#pragma unroll
    for (int j = 0; j < 4; j++) { int i = base + j; if (i < nN) s += g_deg[i]; }
#pragma unroll
    for (int off = 16; off; off >>= 1) s += __shfl_xor_sync(0xffffffffu, s, off);
    __shared__ int ws[8];
    if ((tid & 31) == 0) ws[tid >> 5] = s;
    __syncthreads();
    if (tid == 0) {
        int t = 0;
#pragma unroll
        for (int w = 0; w < 8; w++) t += ws[w];
        g_bsum[b] = t;
    }
}

__global__ void scan_bsums_kernel(int NB) {
    __shared__ int sh[SCAN_NB_MAX];
    int tid = threadIdx.x;
    sh[tid] = (tid < NB) ? g_bsum[tid] : 0;
    __syncthreads();
    for (int off = 1; off < SCAN_NB_MAX; off <<= 1) {
        int v = (tid >= off) ? sh[tid - off] : 0;
        __syncthreads();
        sh[tid] += v;
        __syncthreads();
    }
    g_boff[tid] = tid ? sh[tid - 1] : 0;
}

__global__ void scan_write_kernel(int nN, int Etot) {
    int b = blockIdx.x, tid = threadIdx.x;
    int base = b * SCAN_CHUNK + tid * 4;
    int v[4]; int s = 0;
#pragma unroll
    for (int j = 0; j < 4; j++) {
        int i = base + j;
        v[j] = (i < nN) ? g_deg[i] : 0;
        s += v[j];
    }
    int lane = tid & 31, w = tid >> 5;
    int incl = s;
#pragma unroll
    for (int off = 1; off < 32; off <<= 1) {
        int t = __shfl_up_sync(0xffffffffu, incl, off);
        if (lane >= off) incl += t;
    }
    __shared__ int ws[8], wso[8];
    if (lane == 31) ws[w] = incl;
    __syncthreads();
    if (w == 0 && lane < 8) {
        int x = ws[lane];
        int ix = x;
#pragma unroll
        for (int off = 1; off < 8; off <<= 1) {
            int t = __shfl_up_sync(0xffu, ix, off);
            if (lane >= off) ix += t;
        }
        wso[lane] = ix - x;
    }
    __syncthreads();
    int excl = incl - s + wso[w] + g_boff[b];
#pragma unroll
    for (int j = 0; j < 4; j++) {
        int i = base + j;
        if (i < nN) { g_rowptr[i] = excl; excl += v[j]; }
    }
    if (b == 0 && tid == 0) g_rowptr[nN] = Etot;
}

__global__ void scatter_kernel(int Etot) {
    int i = blockIdx.x * blockDim.x + threadIdx.x;
    if (i >= Etot) return;
    int d   = g_dst[i];
    int pos = g_rowptr[d] + atomicAdd(&g_cnt[d], 1);
    g_csr[pos]  = g_src[i];
    g_dstc[pos] = d;
}

// ---------------- per-layer: h = act(in) @ W ; alpha_s/alpha_d ------------
// Register-tiled: thread = 1 node x 4 channels (float4 W loads).
template <int K, int O, bool PRE>
__global__ void gemm_alpha_kernel(const float* __restrict__ in,
                                  const float* __restrict__ W,
                                  const float* __restrict__ avs,
                                  const float* __restrict__ avd,
                                  const float* __restrict__ pbias,
                                  int nN) {
    constexpr int TPN = O / 4;             // threads per node
    constexpr int BN  = 256 / TPN;         // nodes per block
    constexpr int KP  = K + 1;             // padded row (bank-conflict free)
    __shared__ __align__(16) float Wsh[K * O];
    __shared__ float insh[BN * KP];
    __shared__ float as_sh[O], ad_sh[O];

    int tid = threadIdx.x;
    for (int i = tid; i < K * O; i += 256) Wsh[i] = W[i];
    if (tid < O) { as_sh[tid] = avs[tid]; ad_sh[tid] = avd[tid]; }

    int base = blockIdx.x * BN;
    const float* src = PRE ? g_agg : in;
    for (int i = tid; i < BN * K; i += 256) {
        int nl = i / K, k = i % K;
        int n  = base + nl;
        float v = 0.f;
        if (n < nN) {
            v = src[n * K + k];
            if (PRE) v = fmaxf(v + pbias[k], 0.f);
        }
        insh[nl * KP + k] = v;
    }
    __syncthreads();

    int nl = tid / TPN, ci = tid % TPN;
    int n  = base + nl;

    float4 acc = make_float4(0.f, 0.f, 0.f, 0.f);
#pragma unroll
    for (int k = 0; k < K; k++) {
        float hv = insh[nl * KP + k];
        float4 w = *reinterpret_cast<const float4*>(&Wsh[k * O + ci * 4]);
        acc.x += hv * w.x;
        acc.y += hv * w.y;
        acc.z += hv * w.z;
        acc.w += hv * w.w;
    }

    if (n < nN)
        *reinterpret_cast<float4*>(&g_h[n * O + ci * 4]) = acc;

    float4 a_s = *reinterpret_cast<const float4*>(&as_sh[ci * 4]);
    float4 a_d = *reinterpret_cast<const float4*>(&ad_sh[ci * 4]);
    float ps = acc.x * a_s.x + acc.y * a_s.y + acc.z * a_s.z + acc.w * a_s.w;
    float pd = acc.x * a_d.x + acc.y * a_d.y + acc.z * a_d.z + acc.w * a_d.w;
#pragma unroll
    for (int off = TPN / 2; off; off >>= 1) {
        ps += __shfl_down_sync(0xffffffffu, ps, off);
        pd += __shfl_down_sync(0xffffffffu, pd, off);
    }
    if (ci == 0 && n < nN) {
        g_as[n] = ps;
        g_ad[n] = pd;
    }
}

// ---------------- per-layer: edge-parallel softmax numerators --------------
// w[e] = exp(leakyrelu(as[src] + ad[dst])). Logits bounded -> no max shift.
__global__ void edge_weight_kernel(int Etot) {
    int i = blockIdx.x * blockDim.x + threadIdx.x;
    if (i >= Etot) return;
    int   s = g_csr[i];
    int   d = g_dstc[i];
    float l = g_as[s] + g_ad[d];
    l = l > 0.f ? l : l * 0.2f;
    g_w[i] = __expf(l);
}

// ---------------- per-layer: weighted aggregate (warp/node) ----------------
// Serial loop now: broadcast (csr, w) loads -> gather h -> FMA. Chain depth 1.
template <int O>
__global__ void aggregate_kernel(int nN) {
    int node = (blockIdx.x * blockDim.x + threadIdx.x) >> 5;
    int lane = threadIdx.x & 31;
    if (node >= nN) return;

    int start = g_rowptr[node];
    int end   = g_rowptr[node + 1];

    float sum0 = 0.f, sum1 = 0.f, sum2 = 0.f, sum3 = 0.f;

    if (O == 32) {
        float a0 = 0.f, a1 = 0.f, a2 = 0.f, a3 = 0.f;
        int e = start;
        for (; e + 4 <= end; e += 4) {
            int s0 = g_csr[e],   s1 = g_csr[e + 1];
            int s2 = g_csr[e + 2], s3 = g_csr[e + 3];
            float w0 = g_w[e],   w1 = g_w[e + 1];
            float w2 = g_w[e + 2], w3 = g_w[e + 3];
            sum0 += w0; sum1 += w1; sum2 += w2; sum3 += w3;
            a0 += w0 * g_h[s0 * 32 + lane];
            a1 += w1 * g_h[s1 * 32 + lane];
            a2 += w2 * g_h[s2 * 32 + lane];
            a3 += w3 * g_h[s3 * 32 + lane];
        }
        for (; e < end; e++) {
            int s = g_csr[e];
            float w = g_w[e];
            sum0 += w;
            a0 += w * g_h[s * 32 + lane];
        }
        float sum = (sum0 + sum1) + (sum2 + sum3);
        float inv = 1.f / (sum + 1e-16f);
        g_agg[node * 32 + lane] = ((a0 + a1) + (a2 + a3)) * inv;
    } else {
        float2 a0 = make_float2(0.f, 0.f), a1 = make_float2(0.f, 0.f);
        float2 a2 = make_float2(0.f, 0.f), a3 = make_float2(0.f, 0.f);
        int e = start;
        for (; e + 4 <= end; e += 4) {
            int s0 = g_csr[e],   s1 = g_csr[e + 1];
            int s2 = g_csr[e + 2], s3 = g_csr[e + 3];
            float w0 = g_w[e],   w1 = g_w[e + 1];
            float w2 = g_w[e + 2], w3 = g_w[e + 3];
            sum0 += w0; sum1 += w1; sum2 += w2; sum3 += w3;
            float2 h0 = *reinterpret_cast<const float2*>(&g_h[s0 * 64 + lane * 2]);
            float2 h1 = *reinterpret_cast<const float2*>(&g_h[s1 * 64 + lane * 2]);
            float2 h2 = *reinterpret_cast<const float2*>(&g_h[s2 * 64 + lane * 2]);
            float2 h3 = *reinterpret_cast<const float2*>(&g_h[s3 * 64 + lane * 2]);
            a0.x += w0 * h0.x; a0.y += w0 * h0.y;
            a1.x += w1 * h1.x; a1.y += w1 * h1.y;
            a2.x += w2 * h2.x; a2.y += w2 * h2.y;
            a3.x += w3 * h3.x; a3.y += w3 * h3.y;
        }
        for (; e < end; e++) {
            int s = g_csr[e];
            float w = g_w[e];
            sum0 += w;
            float2 hv = *reinterpret_cast<const float2*>(&g_h[s * 64 + lane * 2]);
            a0.x += w * hv.x; a0.y += w * hv.y;
        }
        float sum = (sum0 + sum1) + (sum2 + sum3);
        float inv = 1.f / (sum + 1e-16f);
        float2 o;
        o.x = ((a0.x + a1.x) + (a2.x + a3.x)) * inv;
        o.y = ((a0.y + a1.y) + (a2.y + a3.y)) * inv;
        *reinterpret_cast<float2*>(&g_agg[node * 64 + lane * 2]) = o;
    }
}

// ---------------- final GEMM: tensor cores (mma.sync bf16, split hi/lo) ----
#define FG_PAD 72   // row stride in elements: conflict-free LDS pattern

__device__ __forceinline__ void mma_bf16(float& d0, float& d1, float& d2, float& d3,
                                         unsigned a0, unsigned a1, unsigned a2, unsigned a3,
                                         unsigned b0, unsigned b1) {
    asm volatile(
        "mma.sync.aligned.m16n8k16.row.col.f32.bf16.bf16.f32 "
        "{%0,%1,%2,%3}, {%4,%5,%6,%7}, {%8,%9}, {%0,%1,%2,%3};"
        : "+f"(d0), "+f"(d1), "+f"(d2), "+f"(d3)
        : "r"(a0), "r"(a1), "r"(a2), "r"(a3), "r"(b0), "r"(b1));
}

__global__ void __launch_bounds__(256)
final_gemm_mma_kernel(const float* __restrict__ b3,
                      const float* __restrict__ Wl,
                      const float* __restrict__ bl,
                      float* __restrict__ out, int nN) {
    extern __shared__ __align__(16) char smem_raw[];
    __nv_bfloat16* Ahi = reinterpret_cast<__nv_bfloat16*>(smem_raw);
    __nv_bfloat16* Alo = Ahi + 128 * FG_PAD;
    __nv_bfloat16* Bhi = Alo + 128 * FG_PAD;   // stored transposed: [chan][k]
    __nv_bfloat16* Blo = Bhi + 128 * FG_PAD;
    __shared__ float blsh[128];

    int tid   = threadIdx.x;
    int cbase = blockIdx.y * 128;
    int nbase = blockIdx.x * 128;

    if (tid < 128) blsh[tid] = bl[cbase + tid];

    for (int i = tid; i < 128 * 64; i += 256) {
        int r = i >> 6, k = i & 63;
        int n = nbase + r;
        float v = 0.f;
        if (n < nN) v = fmaxf(g_agg[n * 64 + k] + b3[k], 0.f);
        __nv_bfloat16 hi = __float2bfloat16_rn(v);
        __nv_bfloat16 lo = __float2bfloat16_rn(v - __bfloat162float(hi));
        Ahi[r * FG_PAD + k] = hi;
        Alo[r * FG_PAD + k] = lo;
    }
    for (int i = tid; i < 64 * 128; i += 256) {
        int k = i >> 7, c = i & 127;
        float w = Wl[k * 512 + cbase + c];
        __nv_bfloat16 hi = __float2bfloat16_rn(w);
        __nv_bfloat16 lo = __float2bfloat16_rn(w - __bfloat162float(hi));
        Bhi[c * FG_PAD + k] = hi;
        Blo[c * FG_PAD + k] = lo;
    }
    __syncthreads();

    int warp = tid >> 5;
    int lane = tid & 31;
    int g    = lane >> 2;
    int t    = lane & 3;
    int R    = warp * 16;

    float d[16][4];
#pragma unroll
    for (int nt = 0; nt < 16; nt++)
#pragma unroll
        for (int j = 0; j < 4; j++) d[nt][j] = 0.f;

#pragma unroll
    for (int kk = 0; kk < 64; kk += 16) {
        const __nv_bfloat16* ah = &Ahi[(R + g) * FG_PAD + kk + t * 2];
        const __nv_bfloat16* al = &Alo[(R + g) * FG_PAD + kk + t * 2];
        unsigned ah0 = *reinterpret_cast<const unsigned*>(ah);
        unsigned ah1 = *reinterpret_cast<const unsigned*>(ah + 8 * FG_PAD);
        unsigned ah2 = *reinterpret_cast<const unsigned*>(ah + 8);
        unsigned ah3 = *reinterpret_cast<const unsigned*>(ah + 8 * FG_PAD + 8);
        unsigned al0 = *reinterpret_cast<const unsigned*>(al);
        unsigned al1 = *reinterpret_cast<const unsigned*>(al + 8 * FG_PAD);
        unsigned al2 = *reinterpret_cast<const unsigned*>(al + 8);
        unsigned al3 = *reinterpret_cast<const unsigned*>(al + 8 * FG_PAD + 8);

#pragma unroll
        for (int nt = 0; nt < 16; nt++) {
            const __nv_bfloat16* bh = &Bhi[(nt * 8 + g) * FG_PAD + kk + t * 2];
            const __nv_bfloat16* blp = &Blo[(nt * 8 + g) * FG_PAD + kk + t * 2];
            unsigned bh0 = *reinterpret_cast<const unsigned*>(bh);
            unsigned bh1 = *reinterpret_cast<const unsigned*>(bh + 8);
            unsigned bl0 = *reinterpret_cast<const unsigned*>(blp);
            unsigned bl1 = *reinterpret_cast<const unsigned*>(blp + 8);
            mma_bf16(d[nt][0], d[nt][1], d[nt][2], d[nt][3],
                     ah0, ah1, ah2, ah3, bh0, bh1);
            mma_bf16(d[nt][0], d[nt][1], d[nt][2], d[nt][3],
                     ah0, ah1, ah2, ah3, bl0, bl1);
            mma_bf16(d[nt][0], d[nt][1], d[nt][2], d[nt][3],
                     al0, al1, al2, al3, bh0, bh1);
        }
    }

    int n0 = nbase + R + g;
    int n1 = n0 + 8;
#pragma unroll
    for (int nt = 0; nt < 16; nt++) {
        int c = nt * 8 + t * 2;
        float b0 = blsh[c], b1 = blsh[c + 1];
        if (n0 < nN) {
            float2 o = make_float2(d[nt][0] + b0, d[nt][1] + b1);
            *reinterpret_cast<float2*>(&out[n0 * 512 + cbase + c]) = o;
        }
        if (n1 < nN) {
            float2 o = make_float2(d[nt][2] + b0, d[nt][3] + b1);
            *reinterpret_cast<float2*>(&out[n1 * 512 + cbase + c]) = o;
        }
    }
}

// ---------------- launch ----------------------------------------------------
extern "C" void kernel_launch(void* const* d_in, const int* in_sizes, int n_in,
                              void* d_out, int out_size) {
    const float* x   = (const float*)d_in[0];
    const void*  ei  = d_in[1];
    // d_in[2] = edge_attr: unused by GATConv (edge_dim=None)
    const float* W1 = (const float*)d_in[3];
    const float* as1 = (const float*)d_in[4];
    const float* ad1 = (const float*)d_in[5];
    const float* b1 = (const float*)d_in[6];
    const float* W2 = (const float*)d_in[7];
    const float* as2 = (const float*)d_in[8];
    const float* ad2 = (const float*)d_in[9];
    const float* b2 = (const float*)d_in[10];
    const float* W3 = (const float*)d_in[11];
    const float* as3 = (const float*)d_in[12];
    const float* ad3 = (const float*)d_in[13];
    const float* b3 = (const float*)d_in[14];
    const float* Wl = (const float*)d_in[15];
    const float* bl = (const float*)d_in[16];
    float* out = (float*)d_out;

    int nN   = in_sizes[0] / 128;      // 100000
    int E    = in_sizes[1] / 2;        // 1600000
    int Etot = E + nN;                 // 1700000
    int NB   = (nN + SCAN_CHUNK - 1) / SCAN_CHUNK;   // 98
    int EB   = (Etot + 255) / 256;

    // ---- CSR build (once per launch, reused by all 3 layers) ----
    detect_kernel<<<1, 32>>>((const int*)ei);
    zero_counts_kernel<<<(nN + 255) / 256, 256>>>(nN);
    build_edges_kernel<<<EB, 256>>>(ei, E, Etot, nN);
    scan_partial_kernel<<<NB, 256>>>(nN);
    scan_bsums_kernel<<<1, SCAN_NB_MAX>>>(NB);
    scan_write_kernel<<<NB, 256>>>(nN, Etot);
    scatter_kernel<<<EB, 256>>>(Etot);

    int aggBlocks = (nN * 32 + 255) / 256;

    // ---- layer 1: 128 -> 32 ----
    gemm_alpha_kernel<128, 32, false><<<(nN + 31) / 32, 256>>>(x, W1, as1, ad1, nullptr, nN);
    edge_weight_kernel<<<EB, 256>>>(Etot);
    aggregate_kernel<32><<<aggBlocks, 256>>>(nN);

    // ---- layer 2: 32 -> 64 ----
    gemm_alpha_kernel<32, 64, true><<<(nN + 15) / 16, 256>>>(nullptr, W2, as2, ad2, b1, nN);
    edge_weight_kernel<<<EB, 256>>>(Etot);
    aggregate_kernel<64><<<aggBlocks, 256>>>(nN);

    // ---- layer 3: 64 -> 64 ----
    gemm_alpha_kernel<64, 64, true><<<(nN + 15) / 16, 256>>>(nullptr, W3, as3, ad3, b2, nN);
    edge_weight_kernel<<<EB, 256>>>(Etot);
    aggregate_kernel<64><<<aggBlocks, 256>>>(nN);

    // ---- final linear on tensor cores ----
    const int FG_SMEM = 4 * 128 * FG_PAD * (int)sizeof(__nv_bfloat16);  // 73728
    cudaFuncSetAttribute(final_gemm_mma_kernel,
                         cudaFuncAttributeMaxDynamicSharedMemorySize, FG_SMEM);
    dim3 fgrid((nN + 127) / 128, 4);
    final_gemm_mma_kernel<<<fgrid, 256, FG_SMEM>>>(b3, Wl, bl, out, nN);
}

// round 9
// speedup vs baseline: 1.0196x; 1.0196x over previous
#include <cuda_runtime.h>
#include <cuda_bf16.h>
#include <cuda_fp16.h>
#include <math.h>

#define NMAX   100000
#define ETOTMX 1700000
#define SCAN_CHUNK 1024
#define SCAN_NB_MAX 128

// ---------------- scratch (static device globals; no allocation) ----------
__device__ int   g_is64;
__device__ int   g_src[ETOTMX];
__device__ int   g_dst[ETOTMX];
__device__ int   g_csr[ETOTMX];
__device__ int   g_dstc[ETOTMX];     // dst id per CSR slot (nearly sorted)
__device__ float g_w[ETOTMX];        // per-edge softmax numerator
__device__ int   g_deg[NMAX];
__device__ int   g_cnt[NMAX];
__device__ int   g_rowptr[NMAX + 1];
__device__ int   g_bsum[SCAN_NB_MAX];
__device__ int   g_boff[SCAN_NB_MAX];
__device__ __align__(16) __half g_hh[NMAX * 64];   // fp16 features (gather operand)
__device__ __align__(16) float  g_agg[NMAX * 64];
__device__ float g_as[NMAX];
__device__ float g_ad[NMAX];

// ---------------- dtype sniff: int64 vs int32 edge_index -------------------
__global__ void detect_kernel(const int* __restrict__ ei32) {
    if (threadIdx.x == 0) {
        int ok = 1;
        for (int i = 0; i < 256; i++)
            if (ei32[2 * i + 1] != 0) { ok = 0; break; }
        g_is64 = ok;
    }
}

// ---------------- graph build ---------------------------------------------
__global__ void zero_counts_kernel(int nN) {
    int i = blockIdx.x * blockDim.x + threadIdx.x;
    if (i < nN) { g_deg[i] = 0; g_cnt[i] = 0; }
}

__global__ void build_edges_kernel(const void* __restrict__ ei, int E, int Etot, int nN) {
    int i = blockIdx.x * blockDim.x + threadIdx.x;
    if (i >= Etot) return;
    int s, d;
    if (i < E) {
        if (g_is64) {
            const long long* p = (const long long*)ei;
            s = (int)p[i]; d = (int)p[E + i];
        } else {
            const int* p = (const int*)ei;
            s = p[i]; d = p[E + i];
        }
        s = min(max(s, 0), nN - 1);
        d = min(max(d, 0), nN - 1);
    } else {
        s = d = i - E;                 // self loops appended
    }
    g_src[i] = s;
    g_dst[i] = d;
    atomicAdd(&g_deg[d], 1);
}

// ---------------- multi-block exclusive scan: g_deg -> g_rowptr ------------
__global__ void scan_partial_kernel(int nN) {
    int b = blockIdx.x, tid = threadIdx.x;
    int base = b * SCAN_CHUNK + tid * 4;
    int s = 0;
#pragma unroll
    for (int j = 0; j < 4; j++) { int i = base + j; if (i < nN) s += g_deg[i]; }
#pragma unroll
    for (int off = 16; off; off >>= 1) s += __shfl_xor_sync(0xffffffffu, s, off);
    __shared__ int ws[8];
    if ((tid & 31) == 0) ws[tid >> 5] = s;
    __syncthreads();
    if (tid == 0) {
        int t = 0;
#pragma unroll
        for (int w = 0; w < 8; w++) t += ws[w];
        g_bsum[b] = t;
    }
}

__global__ void scan_bsums_kernel(int NB) {
    __shared__ int sh[SCAN_NB_MAX];
    int tid = threadIdx.x;
    sh[tid] = (tid < NB) ? g_bsum[tid] : 0;
    __syncthreads();
    for (int off = 1; off < SCAN_NB_MAX; off <<= 1) {
        int v = (tid >= off) ? sh[tid - off] : 0;
        __syncthreads();
        sh[tid] += v;
        __syncthreads();
    }
    g_boff[tid] = tid ? sh[tid - 1] : 0;
}

__global__ void scan_write_kernel(int nN, int Etot) {
    int b = blockIdx.x, tid = threadIdx.x;
    int base = b * SCAN_CHUNK + tid * 4;
    int v[4]; int s = 0;
#pragma unroll
    for (int j = 0; j < 4; j++) {
        int i = base + j;
        v[j] = (i < nN) ? g_deg[i] : 0;
        s += v[j];
    }
    int lane = tid & 31, w = tid >> 5;
    int incl = s;
#pragma unroll
    for (int off = 1; off < 32; off <<= 1) {
        int t = __shfl_up_sync(0xffffffffu, incl, off);
        if (lane >= off) incl += t;
    }
    __shared__ int ws[8], wso[8];
    if (lane == 31) ws[w] = incl;
    __syncthreads();
    if (w == 0 && lane < 8) {
        int x = ws[lane];
        int ix = x;
#pragma unroll
        for (int off = 1; off < 8; off <<= 1) {
            int t = __shfl_up_sync(0xffu, ix, off);
            if (lane >= off) ix += t;
        }
        wso[lane] = ix - x;
    }
    __syncthreads();
    int excl = incl - s + wso[w] + g_boff[b];
#pragma unroll
    for (int j = 0; j < 4; j++) {
        int i = base + j;
        if (i < nN) { g_rowptr[i] = excl; excl += v[j]; }
    }
    if (b == 0 && tid == 0) g_rowptr[nN] = Etot;
}

__global__ void scatter_kernel(int Etot) {
    int i = blockIdx.x * blockDim.x + threadIdx.x;
    if (i >= Etot) return;
    int d   = g_dst[i];
    int pos = g_rowptr[d] + atomicAdd(&g_cnt[d], 1);
    g_csr[pos]  = g_src[i];
    g_dstc[pos] = d;
}

// ---------------- per-layer: h = act(in) @ W ; alpha_s/alpha_d ------------
// Register-tiled: thread = 1 node x 4 channels. h written as fp16 (acc fp32).
template <int K, int O, bool PRE>
__global__ void gemm_alpha_kernel(const float* __restrict__ in,
                                  const float* __restrict__ W,
                                  const float* __restrict__ avs,
                                  const float* __restrict__ avd,
                                  const float* __restrict__ pbias,
                                  int nN) {
    constexpr int TPN = O / 4;             // threads per node
    constexpr int BN  = 256 / TPN;         // nodes per block
    constexpr int KP  = K + 1;             // padded row (bank-conflict free)
    __shared__ __align__(16) float Wsh[K * O];
    __shared__ float insh[BN * KP];
    __shared__ float as_sh[O], ad_sh[O];

    int tid = threadIdx.x;
    for (int i = tid; i < K * O; i += 256) Wsh[i] = W[i];
    if (tid < O) { as_sh[tid] = avs[tid]; ad_sh[tid] = avd[tid]; }

    int base = blockIdx.x * BN;
    const float* src = PRE ? g_agg : in;
    for (int i = tid; i < BN * K; i += 256) {
        int nl = i / K, k = i % K;
        int n  = base + nl;
        float v = 0.f;
        if (n < nN) {
            v = src[n * K + k];
            if (PRE) v = fmaxf(v + pbias[k], 0.f);
        }
        insh[nl * KP + k] = v;
    }
    __syncthreads();

    int nl = tid / TPN, ci = tid % TPN;
    int n  = base + nl;

    float4 acc = make_float4(0.f, 0.f, 0.f, 0.f);
#pragma unroll
    for (int k = 0; k < K; k++) {
        float hv = insh[nl * KP + k];
        float4 w = *reinterpret_cast<const float4*>(&Wsh[k * O + ci * 4]);
        acc.x += hv * w.x;
        acc.y += hv * w.y;
        acc.z += hv * w.z;
        acc.w += hv * w.w;
    }

    if (n < nN) {
        __half2 p0 = __floats2half2_rn(acc.x, acc.y);
        __half2 p1 = __floats2half2_rn(acc.z, acc.w);
        __half2* dst = reinterpret_cast<__half2*>(&g_hh[n * O + ci * 4]);
        dst[0] = p0;
        dst[1] = p1;
    }

    float4 a_s = *reinterpret_cast<const float4*>(&as_sh[ci * 4]);
    float4 a_d = *reinterpret_cast<const float4*>(&ad_sh[ci * 4]);
    float ps = acc.x * a_s.x + acc.y * a_s.y + acc.z * a_s.z + acc.w * a_s.w;
    float pd = acc.x * a_d.x + acc.y * a_d.y + acc.z * a_d.z + acc.w * a_d.w;
#pragma unroll
    for (int off = TPN / 2; off; off >>= 1) {
        ps += __shfl_down_sync(0xffffffffu, ps, off);
        pd += __shfl_down_sync(0xffffffffu, pd, off);
    }
    if (ci == 0 && n < nN) {
        g_as[n] = ps;
        g_ad[n] = pd;
    }
}

// ---------------- per-layer: edge-parallel softmax numerators --------------
__global__ void edge_weight_kernel(int Etot) {
    int i = blockIdx.x * blockDim.x + threadIdx.x;
    if (i >= Etot) return;
    int   s = g_csr[i];
    int   d = g_dstc[i];
    float l = g_as[s] + g_ad[d];
    l = l > 0.f ? l : l * 0.2f;
    g_w[i] = __expf(l);
}

// ---------------- per-layer: weighted aggregate (warp/node, fp16 gathers) --
template <int O>
__global__ void aggregate_kernel(int nN) {
    int node = (blockIdx.x * blockDim.x + threadIdx.x) >> 5;
    int lane = threadIdx.x & 31;
    if (node >= nN) return;

    int start = g_rowptr[node];
    int end   = g_rowptr[node + 1];

    float sum0 = 0.f, sum1 = 0.f, sum2 = 0.f, sum3 = 0.f;

    if (O == 32) {
        float a0 = 0.f, a1 = 0.f, a2 = 0.f, a3 = 0.f;
        int e = start;
        for (; e + 4 <= end; e += 4) {
            int s0 = g_csr[e],     s1 = g_csr[e + 1];
            int s2 = g_csr[e + 2], s3 = g_csr[e + 3];
            float w0 = g_w[e],     w1 = g_w[e + 1];
            float w2 = g_w[e + 2], w3 = g_w[e + 3];
            sum0 += w0; sum1 += w1; sum2 += w2; sum3 += w3;
            a0 += w0 * __half2float(g_hh[s0 * 32 + lane]);
            a1 += w1 * __half2float(g_hh[s1 * 32 + lane]);
            a2 += w2 * __half2float(g_hh[s2 * 32 + lane]);
            a3 += w3 * __half2float(g_hh[s3 * 32 + lane]);
        }
        for (; e < end; e++) {
            int s = g_csr[e];
            float w = g_w[e];
            sum0 += w;
            a0 += w * __half2float(g_hh[s * 32 + lane]);
        }
        float sum = (sum0 + sum1) + (sum2 + sum3);
        float inv = 1.f / (sum + 1e-16f);
        g_agg[node * 32 + lane] = ((a0 + a1) + (a2 + a3)) * inv;
    } else {
        const __half2* hh2 = reinterpret_cast<const __half2*>(g_hh);
        float2 a0 = make_float2(0.f, 0.f), a1 = make_float2(0.f, 0.f);
        float2 a2 = make_float2(0.f, 0.f), a3 = make_float2(0.f, 0.f);
        int e = start;
        for (; e + 4 <= end; e += 4) {
            int s0 = g_csr[e],     s1 = g_csr[e + 1];
            int s2 = g_csr[e + 2], s3 = g_csr[e + 3];
            float w0 = g_w[e],     w1 = g_w[e + 1];
            float w2 = g_w[e + 2], w3 = g_w[e + 3];
            sum0 += w0; sum1 += w1; sum2 += w2; sum3 += w3;
            float2 h0 = __half22float2(hh2[s0 * 32 + lane]);
            float2 h1 = __half22float2(hh2[s1 * 32 + lane]);
            float2 h2 = __half22float2(hh2[s2 * 32 + lane]);
            float2 h3 = __half22float2(hh2[s3 * 32 + lane]);
            a0.x += w0 * h0.x; a0.y += w0 * h0.y;
            a1.x += w1 * h1.x; a1.y += w1 * h1.y;
            a2.x += w2 * h2.x; a2.y += w2 * h2.y;
            a3.x += w3 * h3.x; a3.y += w3 * h3.y;
        }
        for (; e < end; e++) {
            int s = g_csr[e];
            float w = g_w[e];
            sum0 += w;
            float2 hv = __half22float2(hh2[s * 32 + lane]);
            a0.x += w * hv.x; a0.y += w * hv.y;
        }
        float sum = (sum0 + sum1) + (sum2 + sum3);
        float inv = 1.f / (sum + 1e-16f);
        float2 o;
        o.x = ((a0.x + a1.x) + (a2.x + a3.x)) * inv;
        o.y = ((a0.y + a1.y) + (a2.y + a3.y)) * inv;
        *reinterpret_cast<float2*>(&g_agg[node * 64 + lane * 2]) = o;
    }
}

// ---------------- final GEMM: tensor cores (mma.sync bf16, split hi/lo) ----
#define FG_PAD 72   // row stride in elements: conflict-free LDS pattern

__device__ __forceinline__ void mma_bf16(float& d0, float& d1, float& d2, float& d3,
                                         unsigned a0, unsigned a1, unsigned a2, unsigned a3,
                                         unsigned b0, unsigned b1) {
    asm volatile(
        "mma.sync.aligned.m16n8k16.row.col.f32.bf16.bf16.f32 "
        "{%0,%1,%2,%3}, {%4,%5,%6,%7}, {%8,%9}, {%0,%1,%2,%3};"
        : "+f"(d0), "+f"(d1), "+f"(d2), "+f"(d3)
        : "r"(a0), "r"(a1), "r"(a2), "r"(a3), "r"(b0), "r"(b1));
}

__global__ void __launch_bounds__(256)
final_gemm_mma_kernel(const float* __restrict__ b3,
                      const float* __restrict__ Wl,
                      const float* __restrict__ bl,
                      float* __restrict__ out, int nN) {
    extern __shared__ __align__(16) char smem_raw[];
    __nv_bfloat16* Ahi = reinterpret_cast<__nv_bfloat16*>(smem_raw);
    __nv_bfloat16* Alo = Ahi + 128 * FG_PAD;
    __nv_bfloat16* Bhi = Alo + 128 * FG_PAD;   // stored transposed: [chan][k]
    __nv_bfloat16* Blo = Bhi + 128 * FG_PAD;
    __shared__ float blsh[128];

    int tid   = threadIdx.x;
    int cbase = blockIdx.y * 128;
    int nbase = blockIdx.x * 128;

    if (tid < 128) blsh[tid] = bl[cbase + tid];

    for (int i = tid; i < 128 * 64; i += 256) {
        int r = i >> 6, k = i & 63;
        int n = nbase + r;
        float v = 0.f;
        if (n < nN) v = fmaxf(g_agg[n * 64 + k] + b3[k], 0.f);
        __nv_bfloat16 hi = __float2bfloat16_rn(v);
        __nv_bfloat16 lo = __float2bfloat16_rn(v - __bfloat162float(hi));
        Ahi[r * FG_PAD + k] = hi;
        Alo[r * FG_PAD + k] = lo;
    }
    for (int i = tid; i < 64 * 128; i += 256) {
        int k = i >> 7, c = i & 127;
        float w = Wl[k * 512 + cbase + c];
        __nv_bfloat16 hi = __float2bfloat16_rn(w);
        __nv_bfloat16 lo = __float2bfloat16_rn(w - __bfloat162float(hi));
        Bhi[c * FG_PAD + k] = hi;
        Blo[c * FG_PAD + k] = lo;
    }
    __syncthreads();

    int warp = tid >> 5;
    int lane = tid & 31;
    int g    = lane >> 2;
    int t    = lane & 3;
    int R    = warp * 16;

    float d[16][4];
#pragma unroll
    for (int nt = 0; nt < 16; nt++)
#pragma unroll
        for (int j = 0; j < 4; j++) d[nt][j] = 0.f;

#pragma unroll
    for (int kk = 0; kk < 64; kk += 16) {
        const __nv_bfloat16* ah = &Ahi[(R + g) * FG_PAD + kk + t * 2];
        const __nv_bfloat16* al = &Alo[(R + g) * FG_PAD + kk + t * 2];
        unsigned ah0 = *reinterpret_cast<const unsigned*>(ah);
        unsigned ah1 = *reinterpret_cast<const unsigned*>(ah + 8 * FG_PAD);
        unsigned ah2 = *reinterpret_cast<const unsigned*>(ah + 8);
        unsigned ah3 = *reinterpret_cast<const unsigned*>(ah + 8 * FG_PAD + 8);
        unsigned al0 = *reinterpret_cast<const unsigned*>(al);
        unsigned al1 = *reinterpret_cast<const unsigned*>(al + 8 * FG_PAD);
        unsigned al2 = *reinterpret_cast<const unsigned*>(al + 8);
        unsigned al3 = *reinterpret_cast<const unsigned*>(al + 8 * FG_PAD + 8);

#pragma unroll
        for (int nt = 0; nt < 16; nt++) {
            const __nv_bfloat16* bh = &Bhi[(nt * 8 + g) * FG_PAD + kk + t * 2];
            const __nv_bfloat16* blp = &Blo[(nt * 8 + g) * FG_PAD + kk + t * 2];
            unsigned bh0 = *reinterpret_cast<const unsigned*>(bh);
            unsigned bh1 = *reinterpret_cast<const unsigned*>(bh + 8);
            unsigned bl0 = *reinterpret_cast<const unsigned*>(blp);
            unsigned bl1 = *reinterpret_cast<const unsigned*>(blp + 8);
            mma_bf16(d[nt][0], d[nt][1], d[nt][2], d[nt][3],
                     ah0, ah1, ah2, ah3, bh0, bh1);
            mma_bf16(d[nt][0], d[nt][1], d[nt][2], d[nt][3],
                     ah0, ah1, ah2, ah3, bl0, bl1);
            mma_bf16(d[nt][0], d[nt][1], d[nt][2], d[nt][3],
                     al0, al1, al2, al3, bh0, bh1);
        }
    }

    int n0 = nbase + R + g;
    int n1 = n0 + 8;
#pragma unroll
    for (int nt = 0; nt < 16; nt++) {
        int c = nt * 8 + t * 2;
        float b0 = blsh[c], b1 = blsh[c + 1];
        if (n0 < nN) {
            float2 o = make_float2(d[nt][0] + b0, d[nt][1] + b1);
            *reinterpret_cast<float2*>(&out[n0 * 512 + cbase + c]) = o;
        }
        if (n1 < nN) {
            float2 o = make_float2(d[nt][2] + b0, d[nt][3] + b1);
            *reinterpret_cast<float2*>(&out[n1 * 512 + cbase + c]) = o;
        }
    }
}

// ---------------- launch ----------------------------------------------------
extern "C" void kernel_launch(void* const* d_in, const int* in_sizes, int n_in,
                              void* d_out, int out_size) {
    const float* x   = (const float*)d_in[0];
    const void*  ei  = d_in[1];
    // d_in[2] = edge_attr: unused by GATConv (edge_dim=None)
    const float* W1 = (const float*)d_in[3];
    const float* as1 = (const float*)d_in[4];
    const float* ad1 = (const float*)d_in[5];
    const float* b1 = (const float*)d_in[6];
    const float* W2 = (const float*)d_in[7];
    const float* as2 = (const float*)d_in[8];
    const float* ad2 = (const float*)d_in[9];
    const float* b2 = (const float*)d_in[10];
    const float* W3 = (const float*)d_in[11];
    const float* as3 = (const float*)d_in[12];
    const float* ad3 = (const float*)d_in[13];
    const float* b3 = (const float*)d_in[14];
    const float* Wl = (const float*)d_in[15];
    const float* bl = (const float*)d_in[16];
    float* out = (float*)d_out;

    int nN   = in_sizes[0] / 128;      // 100000
    int E    = in_sizes[1] / 2;        // 1600000
    int Etot = E + nN;                 // 1700000
    int NB   = (nN + SCAN_CHUNK - 1) / SCAN_CHUNK;   // 98
    int EB   = (Etot + 255) / 256;

    // ---- CSR build (once per launch, reused by all 3 layers) ----
    detect_kernel<<<1, 32>>>((const int*)ei);
    zero_counts_kernel<<<(nN + 255) / 256, 256>>>(nN);
    build_edges_kernel<<<EB, 256>>>(ei, E, Etot, nN);
    scan_partial_kernel<<<NB, 256>>>(nN);
    scan_bsums_kernel<<<1, SCAN_NB_MAX>>>(NB);
    scan_write_kernel<<<NB, 256>>>(nN, Etot);
    scatter_kernel<<<EB, 256>>>(Etot);

    int aggBlocks = (nN * 32 + 255) / 256;

    // ---- layer 1: 128 -> 32 ----
    gemm_alpha_kernel<128, 32, false><<<(nN + 31) / 32, 256>>>(x, W1, as1, ad1, nullptr, nN);
    edge_weight_kernel<<<EB, 256>>>(Etot);
    aggregate_kernel<32><<<aggBlocks, 256>>>(nN);

    // ---- layer 2: 32 -> 64 ----
    gemm_alpha_kernel<32, 64, true><<<(nN + 15) / 16, 256>>>(nullptr, W2, as2, ad2, b1, nN);
    edge_weight_kernel<<<EB, 256>>>(Etot);
    aggregate_kernel<64><<<aggBlocks, 256>>>(nN);

    // ---- layer 3: 64 -> 64 ----
    gemm_alpha_kernel<64, 64, true><<<(nN + 15) / 16, 256>>>(nullptr, W3, as3, ad3, b2, nN);
    edge_weight_kernel<<<EB, 256>>>(Etot);
    aggregate_kernel<64><<<aggBlocks, 256>>>(nN);

    // ---- final linear on tensor cores ----
    const int FG_SMEM = 4 * 128 * FG_PAD * (int)sizeof(__nv_bfloat16);  // 73728
    cudaFuncSetAttribute(final_gemm_mma_kernel,
                         cudaFuncAttributeMaxDynamicSharedMemorySize, FG_SMEM);
    dim3 fgrid((nN + 127) / 128, 4);
    final_gemm_mma_kernel<<<fgrid, 256, FG_SMEM>>>(b3, Wl, bl, out, nN);
}

// round 10
// speedup vs baseline: 1.0326x; 1.0128x over previous
#include <cuda_runtime.h>
#include <cuda_bf16.h>
#include <cuda_fp16.h>
#include <math.h>

#define NMAX   100000
#define ETOTMX 1700000
#define SCAN_CHUNK 1024
#define SCAN_NB_MAX 128

// ---------------- scratch (static device globals; no allocation) ----------
__device__ int   g_is64;
__device__ int   g_src[ETOTMX];
__device__ int   g_dst[ETOTMX];
__device__ __align__(16) int   g_csr[ETOTMX];
__device__ int   g_dstc[ETOTMX];     // dst id per CSR slot (nearly sorted)
__device__ __align__(16) float g_w[ETOTMX];   // per-edge softmax numerator
__device__ int   g_deg[NMAX];
__device__ int   g_cnt[NMAX];
__device__ int   g_rowptr[NMAX + 1];
__device__ int   g_bsum[SCAN_NB_MAX];
__device__ int   g_boff[SCAN_NB_MAX];
__device__ __align__(16) __half g_hh[NMAX * 64];   // fp16 features (gather operand)
__device__ __align__(16) float  g_agg[NMAX * 64];
__device__ float g_as[NMAX];
__device__ float g_ad[NMAX];

// ---------------- dtype sniff: int64 vs int32 edge_index -------------------
__global__ void detect_kernel(const int* __restrict__ ei32) {
    if (threadIdx.x == 0) {
        int ok = 1;
        for (int i = 0; i < 256; i++)
            if (ei32[2 * i + 1] != 0) { ok = 0; break; }
        g_is64 = ok;
    }
}

// ---------------- graph build ---------------------------------------------
__global__ void zero_counts_kernel(int nN) {
    int i = blockIdx.x * blockDim.x + threadIdx.x;
    if (i < nN) { g_deg[i] = 0; g_cnt[i] = 0; }
}

__global__ void build_edges_kernel(const void* __restrict__ ei, int E, int Etot, int nN) {
    int i = blockIdx.x * blockDim.x + threadIdx.x;
    if (i >= Etot) return;
    int s, d;
    if (i < E) {
        if (g_is64) {
            const long long* p = (const long long*)ei;
            s = (int)p[i]; d = (int)p[E + i];
        } else {
            const int* p = (const int*)ei;
            s = p[i]; d = p[E + i];
        }
        s = min(max(s, 0), nN - 1);
        d = min(max(d, 0), nN - 1);
    } else {
        s = d = i - E;                 // self loops appended
    }
    g_src[i] = s;
    g_dst[i] = d;
    atomicAdd(&g_deg[d], 1);
}

// ---------------- multi-block exclusive scan: g_deg -> g_rowptr ------------
__global__ void scan_partial_kernel(int nN) {
    int b = blockIdx.x, tid = threadIdx.x;
    int base = b * SCAN_CHUNK + tid * 4;
    int s = 0;
#pragma unroll
    for (int j = 0; j < 4; j++) { int i = base + j; if (i < nN) s += g_deg[i]; }
#pragma unroll
    for (int off = 16; off; off >>= 1) s += __shfl_xor_sync(0xffffffffu, s, off);
    __shared__ int ws[8];
    if ((tid & 31) == 0) ws[tid >> 5] = s;
    __syncthreads();
    if (tid == 0) {
        int t = 0;
#pragma unroll
        for (int w = 0; w < 8; w++) t += ws[w];
        g_bsum[b] = t;
    }
}

__global__ void scan_bsums_kernel(int NB) {
    __shared__ int sh[SCAN_NB_MAX];
    int tid = threadIdx.x;
    sh[tid] = (tid < NB) ? g_bsum[tid] : 0;
    __syncthreads();
    for (int off = 1; off < SCAN_NB_MAX; off <<= 1) {
        int v = (tid >= off) ? sh[tid - off] : 0;
        __syncthreads();
        sh[tid] += v;
        __syncthreads();
    }
    g_boff[tid] = tid ? sh[tid - 1] : 0;
}

__global__ void scan_write_kernel(int nN, int Etot) {
    int b = blockIdx.x, tid = threadIdx.x;
    int base = b * SCAN_CHUNK + tid * 4;
    int v[4]; int s = 0;
#pragma unroll
    for (int j = 0; j < 4; j++) {
        int i = base + j;
        v[j] = (i < nN) ? g_deg[i] : 0;
        s += v[j];
    }
    int lane = tid & 31, w = tid >> 5;
    int incl = s;
#pragma unroll
    for (int off = 1; off < 32; off <<= 1) {
        int t = __shfl_up_sync(0xffffffffu, incl, off);
        if (lane >= off) incl += t;
    }
    __shared__ int ws[8], wso[8];
    if (lane == 31) ws[w] = incl;
    __syncthreads();
    if (w == 0 && lane < 8) {
        int x = ws[lane];
        int ix = x;
#pragma unroll
        for (int off = 1; off < 8; off <<= 1) {
            int t = __shfl_up_sync(0xffu, ix, off);
            if (lane >= off) ix += t;
        }
        wso[lane] = ix - x;
    }
    __syncthreads();
    int excl = incl - s + wso[w] + g_boff[b];
#pragma unroll
    for (int j = 0; j < 4; j++) {
        int i = base + j;
        if (i < nN) { g_rowptr[i] = excl; excl += v[j]; }
    }
    if (b == 0 && tid == 0) g_rowptr[nN] = Etot;
}

__global__ void scatter_kernel(int Etot) {
    int i = blockIdx.x * blockDim.x + threadIdx.x;
    if (i >= Etot) return;
    int d   = g_dst[i];
    int pos = g_rowptr[d] + atomicAdd(&g_cnt[d], 1);
    g_csr[pos]  = g_src[i];
    g_dstc[pos] = d;
}

// ---------------- per-layer: h = act(in) @ W ; alpha_s/alpha_d ------------
// Register-tiled: thread = 1 node x 4 channels. h written as fp16 (acc fp32).
template <int K, int O, bool PRE>
__global__ void gemm_alpha_kernel(const float* __restrict__ in,
                                  const float* __restrict__ W,
                                  const float* __restrict__ avs,
                                  const float* __restrict__ avd,
                                  const float* __restrict__ pbias,
                                  int nN) {
    constexpr int TPN = O / 4;             // threads per node
    constexpr int BN  = 256 / TPN;         // nodes per block
    constexpr int KP  = K + 1;             // padded row (bank-conflict free)
    __shared__ __align__(16) float Wsh[K * O];
    __shared__ float insh[BN * KP];
    __shared__ float as_sh[O], ad_sh[O];

    int tid = threadIdx.x;
    for (int i = tid; i < K * O; i += 256) Wsh[i] = W[i];
    if (tid < O) { as_sh[tid] = avs[tid]; ad_sh[tid] = avd[tid]; }

    int base = blockIdx.x * BN;
    const float* src = PRE ? g_agg : in;
    for (int i = tid; i < BN * K; i += 256) {
        int nl = i / K, k = i % K;
        int n  = base + nl;
        float v = 0.f;
        if (n < nN) {
            v = src[n * K + k];
            if (PRE) v = fmaxf(v + pbias[k], 0.f);
        }
        insh[nl * KP + k] = v;
    }
    __syncthreads();

    int nl = tid / TPN, ci = tid % TPN;
    int n  = base + nl;

    float4 acc = make_float4(0.f, 0.f, 0.f, 0.f);
#pragma unroll
    for (int k = 0; k < K; k++) {
        float hv = insh[nl * KP + k];
        float4 w = *reinterpret_cast<const float4*>(&Wsh[k * O + ci * 4]);
        acc.x += hv * w.x;
        acc.y += hv * w.y;
        acc.z += hv * w.z;
        acc.w += hv * w.w;
    }

    if (n < nN) {
        __half2 p0 = __floats2half2_rn(acc.x, acc.y);
        __half2 p1 = __floats2half2_rn(acc.z, acc.w);
        __half2* dst = reinterpret_cast<__half2*>(&g_hh[n * O + ci * 4]);
        dst[0] = p0;
        dst[1] = p1;
    }

    float4 a_s = *reinterpret_cast<const float4*>(&as_sh[ci * 4]);
    float4 a_d = *reinterpret_cast<const float4*>(&ad_sh[ci * 4]);
    float ps = acc.x * a_s.x + acc.y * a_s.y + acc.z * a_s.z + acc.w * a_s.w;
    float pd = acc.x * a_d.x + acc.y * a_d.y + acc.z * a_d.z + acc.w * a_d.w;
#pragma unroll
    for (int off = TPN / 2; off; off >>= 1) {
        ps += __shfl_down_sync(0xffffffffu, ps, off);
        pd += __shfl_down_sync(0xffffffffu, pd, off);
    }
    if (ci == 0 && n < nN) {
        g_as[n] = ps;
        g_ad[n] = pd;
    }
}

// ---------------- per-layer: edge-parallel softmax numerators --------------
__global__ void edge_weight_kernel(int Etot) {
    int i = blockIdx.x * blockDim.x + threadIdx.x;
    if (i >= Etot) return;
    int   s = g_csr[i];
    int   d = g_dstc[i];
    float l = g_as[s] + g_ad[d];
    l = l > 0.f ? l : l * 0.2f;
    g_w[i] = __expf(l);
}

// ---------------- per-layer: weighted aggregate (warp/node) ----------------
// LDG-issue optimized: csr/w loaded as int4/float4 (4 edges per LDG),
// leaving only the irreducible 1 gather LDG per edge. fp16 gathers.
template <int O>
__global__ void aggregate_kernel(int nN) {
    int node = (blockIdx.x * blockDim.x + threadIdx.x) >> 5;
    int lane = threadIdx.x & 31;
    if (node >= nN) return;

    int start = g_rowptr[node];
    int end   = g_rowptr[node + 1];

    float sum0 = 0.f, sum1 = 0.f, sum2 = 0.f, sum3 = 0.f;

    if (O == 32) {
        float a0 = 0.f, a1 = 0.f, a2 = 0.f, a3 = 0.f;
        int e = start;
        // peel to 16B alignment of csr/w index
        for (; e < end && (e & 3); e++) {
            int s = g_csr[e];
            float w = g_w[e];
            sum0 += w;
            a0 += w * __half2float(g_hh[s * 32 + lane]);
        }
        for (; e + 4 <= end; e += 4) {
            int4   s4 = *reinterpret_cast<const int4*>(&g_csr[e]);
            float4 w4 = *reinterpret_cast<const float4*>(&g_w[e]);
            sum0 += w4.x; sum1 += w4.y; sum2 += w4.z; sum3 += w4.w;
            a0 += w4.x * __half2float(g_hh[s4.x * 32 + lane]);
            a1 += w4.y * __half2float(g_hh[s4.y * 32 + lane]);
            a2 += w4.z * __half2float(g_hh[s4.z * 32 + lane]);
            a3 += w4.w * __half2float(g_hh[s4.w * 32 + lane]);
        }
        for (; e < end; e++) {
            int s = g_csr[e];
            float w = g_w[e];
            sum0 += w;
            a0 += w * __half2float(g_hh[s * 32 + lane]);
        }
        float sum = (sum0 + sum1) + (sum2 + sum3);
        float inv = 1.f / (sum + 1e-16f);
        g_agg[node * 32 + lane] = ((a0 + a1) + (a2 + a3)) * inv;
    } else {
        const __half2* hh2 = reinterpret_cast<const __half2*>(g_hh);
        float2 a0 = make_float2(0.f, 0.f), a1 = make_float2(0.f, 0.f);
        float2 a2 = make_float2(0.f, 0.f), a3 = make_float2(0.f, 0.f);
        int e = start;
        for (; e < end && (e & 3); e++) {
            int s = g_csr[e];
            float w = g_w[e];
            sum0 += w;
            float2 hv = __half22float2(hh2[s * 32 + lane]);
            a0.x += w * hv.x; a0.y += w * hv.y;
        }
        for (; e + 4 <= end; e += 4) {
            int4   s4 = *reinterpret_cast<const int4*>(&g_csr[e]);
            float4 w4 = *reinterpret_cast<const float4*>(&g_w[e]);
            sum0 += w4.x; sum1 += w4.y; sum2 += w4.z; sum3 += w4.w;
            float2 h0 = __half22float2(hh2[s4.x * 32 + lane]);
            float2 h1 = __half22float2(hh2[s4.y * 32 + lane]);
            float2 h2 = __half22float2(hh2[s4.z * 32 + lane]);
            float2 h3 = __half22float2(hh2[s4.w * 32 + lane]);
            a0.x += w4.x * h0.x; a0.y += w4.x * h0.y;
            a1.x += w4.y * h1.x; a1.y += w4.y * h1.y;
            a2.x += w4.z * h2.x; a2.y += w4.z * h2.y;
            a3.x += w4.w * h3.x; a3.y += w4.w * h3.y;
        }
        for (; e < end; e++) {
            int s = g_csr[e];
            float w = g_w[e];
            sum0 += w;
            float2 hv = __half22float2(hh2[s * 32 + lane]);
            a0.x += w * hv.x; a0.y += w * hv.y;
        }
        float sum = (sum0 + sum1) + (sum2 + sum3);
        float inv = 1.f / (sum + 1e-16f);
        float2 o;
        o.x = ((a0.x + a1.x) + (a2.x + a3.x)) * inv;
        o.y = ((a0.y + a1.y) + (a2.y + a3.y)) * inv;
        *reinterpret_cast<float2*>(&g_agg[node * 64 + lane * 2]) = o;
    }
}

// ---------------- final GEMM: tensor cores (mma.sync bf16, split hi/lo) ----
#define FG_PAD 72   // row stride in elements: conflict-free LDS pattern

__device__ __forceinline__ void mma_bf16(float& d0, float& d1, float& d2, float& d3,
                                         unsigned a0, unsigned a1, unsigned a2, unsigned a3,
                                         unsigned b0, unsigned b1) {
    asm volatile(
        "mma.sync.aligned.m16n8k16.row.col.f32.bf16.bf16.f32 "
        "{%0,%1,%2,%3}, {%4,%5,%6,%7}, {%8,%9}, {%0,%1,%2,%3};"
        : "+f"(d0), "+f"(d1), "+f"(d2), "+f"(d3)
        : "r"(a0), "r"(a1), "r"(a2), "r"(a3), "r"(b0), "r"(b1));
}

__global__ void __launch_bounds__(256)
final_gemm_mma_kernel(const float* __restrict__ b3,
                      const float* __restrict__ Wl,
                      const float* __restrict__ bl,
                      float* __restrict__ out, int nN) {
    extern __shared__ __align__(16) char smem_raw[];
    __nv_bfloat16* Ahi = reinterpret_cast<__nv_bfloat16*>(smem_raw);
    __nv_bfloat16* Alo = Ahi + 128 * FG_PAD;
    __nv_bfloat16* Bhi = Alo + 128 * FG_PAD;   // stored transposed: [chan][k]
    __nv_bfloat16* Blo = Bhi + 128 * FG_PAD;
    __shared__ float blsh[128];

    int tid   = threadIdx.x;
    int cbase = blockIdx.y * 128;
    int nbase = blockIdx.x * 128;

    if (tid < 128) blsh[tid] = bl[cbase + tid];

    for (int i = tid; i < 128 * 64; i += 256) {
        int r = i >> 6, k = i & 63;
        int n = nbase + r;
        float v = 0.f;
        if (n < nN) v = fmaxf(g_agg[n * 64 + k] + b3[k], 0.f);
        __nv_bfloat16 hi = __float2bfloat16_rn(v);
        __nv_bfloat16 lo = __float2bfloat16_rn(v - __bfloat162float(hi));
        Ahi[r * FG_PAD + k] = hi;
        Alo[r * FG_PAD + k] = lo;
    }
    for (int i = tid; i < 64 * 128; i += 256) {
        int k = i >> 7, c = i & 127;
        float w = Wl[k * 512 + cbase + c];
        __nv_bfloat16 hi = __float2bfloat16_rn(w);
        __nv_bfloat16 lo = __float2bfloat16_rn(w - __bfloat162float(hi));
        Bhi[c * FG_PAD + k] = hi;
        Blo[c * FG_PAD + k] = lo;
    }
    __syncthreads();

    int warp = tid >> 5;
    int lane = tid & 31;
    int g    = lane >> 2;
    int t    = lane & 3;
    int R    = warp * 16;

    float d[16][4];
#pragma unroll
    for (int nt = 0; nt < 16; nt++)
#pragma unroll
        for (int j = 0; j < 4; j++) d[nt][j] = 0.f;

#pragma unroll
    for (int kk = 0; kk < 64; kk += 16) {
        const __nv_bfloat16* ah = &Ahi[(R + g) * FG_PAD + kk + t * 2];
        const __nv_bfloat16* al = &Alo[(R + g) * FG_PAD + kk + t * 2];
        unsigned ah0 = *reinterpret_cast<const unsigned*>(ah);
        unsigned ah1 = *reinterpret_cast<const unsigned*>(ah + 8 * FG_PAD);
        unsigned ah2 = *reinterpret_cast<const unsigned*>(ah + 8);
        unsigned ah3 = *reinterpret_cast<const unsigned*>(ah + 8 * FG_PAD + 8);
        unsigned al0 = *reinterpret_cast<const unsigned*>(al);
        unsigned al1 = *reinterpret_cast<const unsigned*>(al + 8 * FG_PAD);
        unsigned al2 = *reinterpret_cast<const unsigned*>(al + 8);
        unsigned al3 = *reinterpret_cast<const unsigned*>(al + 8 * FG_PAD + 8);

#pragma unroll
        for (int nt = 0; nt < 16; nt++) {
            const __nv_bfloat16* bh = &Bhi[(nt * 8 + g) * FG_PAD + kk + t * 2];
            const __nv_bfloat16* blp = &Blo[(nt * 8 + g) * FG_PAD + kk + t * 2];
            unsigned bh0 = *reinterpret_cast<const unsigned*>(bh);
            unsigned bh1 = *reinterpret_cast<const unsigned*>(bh + 8);
            unsigned bl0 = *reinterpret_cast<const unsigned*>(blp);
            unsigned bl1 = *reinterpret_cast<const unsigned*>(blp + 8);
            mma_bf16(d[nt][0], d[nt][1], d[nt][2], d[nt][3],
                     ah0, ah1, ah2, ah3, bh0, bh1);
            mma_bf16(d[nt][0], d[nt][1], d[nt][2], d[nt][3],
                     ah0, ah1, ah2, ah3, bl0, bl1);
            mma_bf16(d[nt][0], d[nt][1], d[nt][2], d[nt][3],
                     al0, al1, al2, al3, bh0, bh1);
        }
    }

    int n0 = nbase + R + g;
    int n1 = n0 + 8;
#pragma unroll
    for (int nt = 0; nt < 16; nt++) {
        int c = nt * 8 + t * 2;
        float b0 = blsh[c], b1 = blsh[c + 1];
        if (n0 < nN) {
            float2 o = make_float2(d[nt][0] + b0, d[nt][1] + b1);
            *reinterpret_cast<float2*>(&out[n0 * 512 + cbase + c]) = o;
        }
        if (n1 < nN) {
            float2 o = make_float2(d[nt][2] + b0, d[nt][3] + b1);
            *reinterpret_cast<float2*>(&out[n1 * 512 + cbase + c]) = o;
        }
    }
}

// ---------------- launch ----------------------------------------------------
extern "C" void kernel_launch(void* const* d_in, const int* in_sizes, int n_in,
                              void* d_out, int out_size) {
    const float* x   = (const float*)d_in[0];
    const void*  ei  = d_in[1];
    // d_in[2] = edge_attr: unused by GATConv (edge_dim=None)
    const float* W1 = (const float*)d_in[3];
    const float* as1 = (const float*)d_in[4];
    const float* ad1 = (const float*)d_in[5];
    const float* b1 = (const float*)d_in[6];
    const float* W2 = (const float*)d_in[7];
    const float* as2 = (const float*)d_in[8];
    const float* ad2 = (const float*)d_in[9];
    const float* b2 = (const float*)d_in[10];
    const float* W3 = (const float*)d_in[11];
    const float* as3 = (const float*)d_in[12];
    const float* ad3 = (const float*)d_in[13];
    const float* b3 = (const float*)d_in[14];
    const float* Wl = (const float*)d_in[15];
    const float* bl = (const float*)d_in[16];
    float* out = (float*)d_out;

    int nN   = in_sizes[0] / 128;      // 100000
    int E    = in_sizes[1] / 2;        // 1600000
    int Etot = E + nN;                 // 1700000
    int NB   = (nN + SCAN_CHUNK - 1) / SCAN_CHUNK;   // 98
    int EB   = (Etot + 255) / 256;

    // ---- CSR build (once per launch, reused by all 3 layers) ----
    detect_kernel<<<1, 32>>>((const int*)ei);
    zero_counts_kernel<<<(nN + 255) / 256, 256>>>(nN);
    build_edges_kernel<<<EB, 256>>>(ei, E, Etot, nN);
    scan_partial_kernel<<<NB, 256>>>(nN);
    scan_bsums_kernel<<<1, SCAN_NB_MAX>>>(NB);
    scan_write_kernel<<<NB, 256>>>(nN, Etot);
    scatter_kernel<<<EB, 256>>>(Etot);

    int aggBlocks = (nN * 32 + 255) / 256;

    // ---- layer 1: 128 -> 32 ----
    gemm_alpha_kernel<128, 32, false><<<(nN + 31) / 32, 256>>>(x, W1, as1, ad1, nullptr, nN);
    edge_weight_kernel<<<EB, 256>>>(Etot);
    aggregate_kernel<32><<<aggBlocks, 256>>>(nN);

    // ---- layer 2: 32 -> 64 ----
    gemm_alpha_kernel<32, 64, true><<<(nN + 15) / 16, 256>>>(nullptr, W2, as2, ad2, b1, nN);
    edge_weight_kernel<<<EB, 256>>>(Etot);
    aggregate_kernel<64><<<aggBlocks, 256>>>(nN);

    // ---- layer 3: 64 -> 64 ----
    gemm_alpha_kernel<64, 64, true><<<(nN + 15) / 16, 256>>>(nullptr, W3, as3, ad3, b2, nN);
    edge_weight_kernel<<<EB, 256>>>(Etot);
    aggregate_kernel<64><<<aggBlocks, 256>>>(nN);

    // ---- final linear on tensor cores ----
    const int FG_SMEM = 4 * 128 * FG_PAD * (int)sizeof(__nv_bfloat16);  // 73728
    cudaFuncSetAttribute(final_gemm_mma_kernel,
                         cudaFuncAttributeMaxDynamicSharedMemorySize, FG_SMEM);
    dim3 fgrid((nN + 127) / 128, 4);
    final_gemm_mma_kernel<<<fgrid, 256, FG_SMEM>>>(b3, Wl, bl, out, nN);
}